// round 13
// baseline (speedup 1.0000x reference)
#include <cuda_runtime.h>
#include <cuda_fp16.h>
#include <cstdint>

#define B 8
#define E 256
#define T 4096
#define H 8
#define GC 32
#define KW 3
#define CTT 256

// attention tiling
#define QM 64
#define KN 64
#define NT (T / KN)          // 64
#define QSTR 264             // staging stride (halves)
#define KSTR 264             // K row: 256 data (hi only) + 8 pad
#define VSTR 72              // V row: 64 keys + 8 pad
#define PSTR 72

// attn smem byte offsets
#define PH_OFF 0u
#define SL_OFF 9216u
#define KV_OFF 10240u
#define KV_VH 33792u               // K tile bytes (64*528)
#define KVBUF_BYTES 70656u         // K 33792 + Vh 36864
#define ATT_SMEM (KV_OFF + 2u * KVBUF_BYTES)   // 151552

// fc smem
#define FC_AH 0u
#define FC_AL 18432u
#define FC_BH 36864u
#define FC_BL 55296u
#define FC_BUF 73728u
#define FC_SMEM (2u * FC_BUF)   // 147456

// ---------------- device scratch ----------------
__device__ __align__(16) __half g_qh[(size_t)B * T * E];
__device__ __align__(16) __half g_kh[(size_t)B * T * E];     // hi only
__device__ __align__(16) __half g_vh[(size_t)B * E * T];     // [B,d,t]
__device__ __align__(16) __half g_oh[(size_t)B * T * E];
__device__ __align__(16) __half g_ol[(size_t)B * T * E];
__device__ __align__(16) __half g_wh[E * E];
__device__ __align__(16) __half g_wl[E * E];

// ---------------- helpers ----------------
__device__ __forceinline__ uint32_t smem_u32(const void* p) {
    uint32_t a;
    asm("{ .reg .u64 t; cvta.to.shared.u64 t, %1; cvt.u32.u64 %0, t; }" : "=r"(a) : "l"(p));
    return a;
}
__device__ __forceinline__ void ldsm_x4(uint32_t* r, uint32_t a) {
    asm volatile("ldmatrix.sync.aligned.m8n8.x4.shared.b16 {%0,%1,%2,%3}, [%4];"
        : "=r"(r[0]), "=r"(r[1]), "=r"(r[2]), "=r"(r[3]) : "r"(a));
}
__device__ __forceinline__ void ldsm_x2(uint32_t* r, uint32_t a) {
    asm volatile("ldmatrix.sync.aligned.m8n8.x2.shared.b16 {%0,%1}, [%2];"
        : "=r"(r[0]), "=r"(r[1]) : "r"(a));
}
__device__ __forceinline__ void mma16816(float* d, const uint32_t* a, const uint32_t* b) {
    asm volatile("mma.sync.aligned.m16n8k16.row.col.f32.f16.f16.f32 "
        "{%0,%1,%2,%3}, {%4,%5,%6,%7}, {%8,%9}, {%0,%1,%2,%3};"
        : "+f"(d[0]), "+f"(d[1]), "+f"(d[2]), "+f"(d[3])
        : "r"(a[0]), "r"(a[1]), "r"(a[2]), "r"(a[3]), "r"(b[0]), "r"(b[1]));
}
__device__ __forceinline__ void cp16(uint32_t dst, const void* src) {
    asm volatile("cp.async.cg.shared.global [%0], [%1], 16;" :: "r"(dst), "l"(src));
}
#define CP_COMMIT() asm volatile("cp.async.commit_group;" ::: "memory")
#define CP_WAIT1()  asm volatile("cp.async.wait_group 1;" ::: "memory")

__device__ __forceinline__ uint32_t pack_h16(float a, float b) {
    __half2 t = __floats2half2_rn(a, b);
    return *reinterpret_cast<uint32_t*>(&t);
}

// ---------------------------------------------------------------------------
// Kernel 1: grouped conv1d, one projection per block.
// proj 0: q -> fp16 [B,T,E]; proj 1: k -> fp16 [B,T,E];
// proj 2: v -> fp16 transposed [B,E,T].
// ---------------------------------------------------------------------------
__global__ __launch_bounds__(256) void conv_qkv_kernel(
    const float* __restrict__ x,
    const float* __restrict__ wq, const float* __restrict__ bq,
    const float* __restrict__ wk, const float* __restrict__ bk,
    const float* __restrict__ wv, const float* __restrict__ bv)
{
    extern __shared__ float sm[];
    float* sx  = sm;
    float* swT = sx + GC * (CTT + 2);
    float* st  = swT + GC * GC * KW;

    const int tid = threadIdx.x;
    const int b = blockIdx.z;
    const int proj = blockIdx.y / H;
    const int g = blockIdx.y % H;
    const int t0 = blockIdx.x * CTT;

    const float* wsrc = (proj == 0) ? wq : (proj == 1) ? wk : wv;
    const float* bsrc = (proj == 0) ? bq : (proj == 1) ? bk : bv;

    const int gw = g * GC * GC * KW;
    for (int i = tid; i < GC * GC * KW; i += 256) {
        int oc = i & 31, r = i >> 5;
        swT[r * 32 + oc] = wsrc[gw + oc * (GC * KW) + r];
    }
    for (int i = tid; i < GC * (CTT + 2); i += 256) {
        int ic = i / (CTT + 2), tt = i % (CTT + 2);
        int t = t0 + tt - 1;
        sx[i] = (t >= 0 && t < T) ? x[((size_t)b * E + g * GC + ic) * T + t] : 0.f;
    }
    __syncthreads();

    float acc[GC];
#pragma unroll
    for (int oc = 0; oc < GC; oc++) acc[oc] = 0.f;

    const int p = tid;
    for (int ic = 0; ic < GC; ic++) {
        float xk[3];
        xk[0] = sx[ic * (CTT + 2) + p];
        xk[1] = sx[ic * (CTT + 2) + p + 1];
        xk[2] = sx[ic * (CTT + 2) + p + 2];
#pragma unroll
        for (int kw = 0; kw < 3; kw++) {
            const float* wrow = &swT[(ic * 3 + kw) * 32];
#pragma unroll
            for (int oc4 = 0; oc4 < 8; oc4++) {
                float4 w4 = *(const float4*)&wrow[oc4 * 4];
                acc[oc4 * 4 + 0] += xk[kw] * w4.x;
                acc[oc4 * 4 + 1] += xk[kw] * w4.y;
                acc[oc4 * 4 + 2] += xk[kw] * w4.z;
                acc[oc4 * 4 + 3] += xk[kw] * w4.w;
            }
        }
    }

    if (proj == 2) {
#pragma unroll
        for (int oc = 0; oc < GC; oc++) {
            float v = acc[oc] + bsrc[g * GC + oc];
            g_vh[((size_t)b * E + g * GC + oc) * T + t0 + p] = __float2half(v);
        }
        return;
    }

#pragma unroll
    for (int oc = 0; oc < GC; oc++) st[p * 33 + oc] = acc[oc] + bsrc[g * GC + oc];
    __syncthreads();

    __half* dst = (proj == 0) ? g_qh : g_kh;
    const size_t ob = ((size_t)b * T + t0) * E + g * GC;
    for (int i = tid; i < CTT * GC; i += 256) {
        int t = i >> 5, oc = i & 31;
        dst[ob + (size_t)t * E + oc] = __float2half(st[t * 33 + oc]);
    }
}

// ---------------------------------------------------------------------------
// Kernel 1b: split w_fc into fp16 hi/lo
// ---------------------------------------------------------------------------
__global__ void wsplit_kernel(const float* __restrict__ wfc)
{
    int i = blockIdx.x * 256 + threadIdx.x;
    float v = wfc[i];
    __half hi = __float2half(v);
    g_wh[i] = hi;
    g_wl[i] = __float2half(v - __half2float(hi));
}

// ---------------------------------------------------------------------------
// Kernel 2: flash attention. S = Qh*Kh (Q fragments in registers);
// PV = Ph*Vh (single term). No-max softmax. 64-key tiles, double-buffered.
// ---------------------------------------------------------------------------
__device__ __forceinline__ void load_tile_kv(uint32_t sb, int b, int t, int buf, int tid)
{
    const uint32_t base = sb + KV_OFF + (uint32_t)buf * KVBUF_BYTES;
    const char* ksrc = (const char*)(g_kh + ((size_t)(b * T + t * KN)) * E);
    for (int i = tid; i < 2048; i += 256) {
        int key = i >> 5, c = i & 31;
        cp16(base + key * 528 + c * 16, ksrc + (size_t)key * 512 + c * 16);
    }
    const char* vhsrc = (const char*)(g_vh + (size_t)b * E * T + (size_t)t * KN);
    for (int i = tid; i < 2048; i += 256) {
        int d = i >> 3, c = i & 7;
        cp16(base + KV_VH + d * 144 + c * 16, vhsrc + (size_t)d * T * 2 + c * 16);
    }
    CP_COMMIT();
}

__global__ __launch_bounds__(256, 1) void attn_kernel()
{
    extern __shared__ char smem[];
    const uint32_t sb = smem_u32(smem);
    float* sL = (float*)(smem + SL_OFF);     // [2][64]

    const int tid = threadIdx.x;
    const int wid = tid >> 5, lane = tid & 31;
    const int b = blockIdx.y;
    const int q0 = blockIdx.x * QM;
    const float scale = 0.0625f;

    // S grid: warp = 16 rows x 32 cols. PV grid: warp = 32 rows x 64 d.
    const int r0 = (wid >> 1) * 16, c0 = (wid & 1) * 32;
    const int rr0 = (wid >> 2) * 32, dd0 = (wid & 3) * 64;

    const uint32_t qrow = (uint32_t)(lane & 15);
    const uint32_t qcchunk = (uint32_t)((lane >> 4) << 3);
    const uint32_t brow8 = (uint32_t)((lane & 7) + ((lane >> 4) << 3));
    const uint32_t bcol8 = (uint32_t)(lane & 8);

    // ---- stage Q into KV area, ldmatrix into registers, then release ----
    uint32_t qf[16][4];
    {
        for (int i = tid; i < 2048; i += 256) {
            int r = i >> 5, c8 = i & 31;
            *(uint4*)(smem + KV_OFF + r * (QSTR * 2) + c8 * 16) =
                *(const uint4*)((const char*)(g_qh + ((size_t)(b * T + q0 + r)) * E) + c8 * 16);
        }
        __syncthreads();
#pragma unroll
        for (int kk = 0; kk < 16; kk++)
            ldsm_x4(qf[kk], sb + KV_OFF +
                    (((uint32_t)r0 + qrow) * QSTR + kk * 16 + qcchunk) * 2);
        __syncthreads();
    }

    load_tile_kv(sb, b, 0, 0, tid);

    float oacc[2][8][4];
#pragma unroll
    for (int mi = 0; mi < 2; mi++)
#pragma unroll
        for (int j = 0; j < 8; j++)
#pragma unroll
            for (int e = 0; e < 4; e++) oacc[mi][j][e] = 0.f;
    float lsum[2] = {0.f, 0.f};

    for (int t = 0; t < NT; t++) {
        if (t + 1 < NT) load_tile_kv(sb, b, t + 1, (t + 1) & 1, tid);
        else CP_COMMIT();
        CP_WAIT1();
        __syncthreads();

        const uint32_t kb = sb + KV_OFF + (uint32_t)(t & 1) * KVBUF_BYTES;

        // ---- S = Qh*Kh ----
        float sacc[4][4];
#pragma unroll
        for (int j = 0; j < 4; j++)
#pragma unroll
            for (int e = 0; e < 4; e++) sacc[j][e] = 0.f;

#pragma unroll
        for (int kk = 0; kk < 16; kk++) {
            const int d0 = kk * 16;
#pragma unroll
            for (int jp = 0; jp < 2; jp++) {
                uint32_t key = (uint32_t)(c0 + 16 * jp) + brow8;
                uint32_t bb[4];
                ldsm_x4(bb, kb + (key * KSTR + d0 + bcol8) * 2);
                mma16816(sacc[2 * jp],     qf[kk], bb);
                mma16816(sacc[2 * jp + 1], qf[kk], bb + 2);
            }
        }

        // ---- P = exp(S*scale); l; store Ph -> smem ----
#pragma unroll
        for (int j = 0; j < 4; j++) {
            float p0 = __expf(sacc[j][0] * scale);
            float p1 = __expf(sacc[j][1] * scale);
            float p2 = __expf(sacc[j][2] * scale);
            float p3 = __expf(sacc[j][3] * scale);
            lsum[0] += p0 + p1;
            lsum[1] += p2 + p3;
            int row = r0 + (lane >> 2);
            int col = c0 + 8 * j + ((lane & 3) << 1);
            *(uint32_t*)(smem + PH_OFF + row * (PSTR * 2) + col * 2) = pack_h16(p0, p1);
            *(uint32_t*)(smem + PH_OFF + (row + 8) * (PSTR * 2) + col * 2) = pack_h16(p2, p3);
        }
        __syncthreads();

        // ---- O += Ph*Vh ----
#pragma unroll
        for (int kk2 = 0; kk2 < 4; kk2++) {
            const int key0 = kk2 * 16;
            uint32_t ph[2][4];
#pragma unroll
            for (int mi = 0; mi < 2; mi++) {
                uint32_t prow = (uint32_t)(rr0 + 16 * mi) + qrow;
                ldsm_x4(ph[mi], sb + PH_OFF + (prow * PSTR + key0 + qcchunk) * 2);
            }
#pragma unroll
            for (int jp = 0; jp < 4; jp++) {
                uint32_t drow = (uint32_t)(dd0 + 16 * jp) + brow8;
                uint32_t bb[4];
                ldsm_x4(bb, kb + KV_VH + (drow * VSTR + key0 + bcol8) * 2);
#pragma unroll
                for (int mi = 0; mi < 2; mi++) {
                    mma16816(oacc[mi][2 * jp],     ph[mi], bb);
                    mma16816(oacc[mi][2 * jp + 1], ph[mi], bb + 2);
                }
            }
        }
        __syncthreads();
    }

    // ---- l reduction ----
    lsum[0] += __shfl_xor_sync(0xffffffffu, lsum[0], 1);
    lsum[0] += __shfl_xor_sync(0xffffffffu, lsum[0], 2);
    lsum[1] += __shfl_xor_sync(0xffffffffu, lsum[1], 1);
    lsum[1] += __shfl_xor_sync(0xffffffffu, lsum[1], 2);
    if ((lane & 3) == 0) {
        sL[(wid & 1) * 64 + r0 + (lane >> 2)] = lsum[0];
        sL[(wid & 1) * 64 + r0 + 8 + (lane >> 2)] = lsum[1];
    }
    __syncthreads();

    // ---- O /= l, write fp16 hi/lo ----
#pragma unroll
    for (int mi = 0; mi < 2; mi++) {
        int rA = rr0 + 16 * mi + (lane >> 2);
        int rB = rA + 8;
        float invA = 1.f / (sL[rA] + sL[64 + rA]);
        float invB = 1.f / (sL[rB] + sL[64 + rB]);
        size_t oa = ((size_t)(b * T + q0 + rA)) * E;
        size_t ob = ((size_t)(b * T + q0 + rB)) * E;
#pragma unroll
        for (int j = 0; j < 8; j++) {
            int col = dd0 + 8 * j + ((lane & 3) << 1);
            float a0 = oacc[mi][j][0] * invA, a1 = oacc[mi][j][1] * invA;
            float b0 = oacc[mi][j][2] * invB, b1 = oacc[mi][j][3] * invB;
            __half ha0 = __float2half(a0), ha1 = __float2half(a1);
            __half hb0 = __float2half(b0), hb1 = __float2half(b1);
            *(uint32_t*)(g_oh + oa + col) = pack_h16(a0, a1);
            *(uint32_t*)(g_ol + oa + col) =
                pack_h16(a0 - __half2float(ha0), a1 - __half2float(ha1));
            *(uint32_t*)(g_oh + ob + col) = pack_h16(b0, b1);
            *(uint32_t*)(g_ol + ob + col) =
                pack_h16(b0 - __half2float(hb0), b1 - __half2float(hb1));
        }
    }
}

// ---------------------------------------------------------------------------
// Kernel 3: fc_out via fp16 mma 3-term. CTA 128r x 128c, K=256 in 4 chunks.
// ---------------------------------------------------------------------------
__device__ __forceinline__ void load_fc(uint32_t sb, int r0, int c0, int c, int buf, int tid)
{
    const uint32_t base = sb + (uint32_t)buf * FC_BUF;
    for (int i = tid; i < 1024; i += 256) {
        int row = i >> 3, seg = i & 7;
        const size_t ao = (size_t)(r0 + row) * E + c * 64;
        const size_t bo = (size_t)(c0 + row) * E + c * 64;
        cp16(base + FC_AH + row * 144 + seg * 16, (const char*)(g_oh + ao) + seg * 16);
        cp16(base + FC_AL + row * 144 + seg * 16, (const char*)(g_ol + ao) + seg * 16);
        cp16(base + FC_BH + row * 144 + seg * 16, (const char*)(g_wh + bo) + seg * 16);
        cp16(base + FC_BL + row * 144 + seg * 16, (const char*)(g_wl + bo) + seg * 16);
    }
    CP_COMMIT();
}

__global__ __launch_bounds__(256, 1) void fc_kernel(
    const float* __restrict__ bfc, float* __restrict__ out)
{
    extern __shared__ char smem[];
    const uint32_t sb = smem_u32(smem);

    const int tid = threadIdx.x;
    const int wid = tid >> 5, lane = tid & 31;
    const int r0 = blockIdx.y * 128, c0 = blockIdx.x * 128;
    const int wr2 = wid >> 1, wc2 = wid & 1;

    float acc[2][8][4];
#pragma unroll
    for (int mi = 0; mi < 2; mi++)
#pragma unroll
        for (int j = 0; j < 8; j++)
#pragma unroll
            for (int e = 0; e < 4; e++) acc[mi][j][e] = 0.f;

    const uint32_t qrow = (uint32_t)(lane & 15);
    const uint32_t qcchunk = (uint32_t)((lane >> 4) << 3);

    load_fc(sb, r0, c0, 0, 0, tid);

    for (int c = 0; c < 4; c++) {
        if (c + 1 < 4) load_fc(sb, r0, c0, c + 1, (c + 1) & 1, tid);
        else CP_COMMIT();
        CP_WAIT1();
        __syncthreads();
        const uint32_t base = sb + (uint32_t)(c & 1) * FC_BUF;

#pragma unroll
        for (int kk = 0; kk < 4; kk++) {
            const int d0 = kk * 16;
            uint32_t ah[2][4], al[2][4];
#pragma unroll
            for (int mi = 0; mi < 2; mi++) {
                uint32_t aaddr = base + FC_AH +
                    (((uint32_t)(wr2 * 32 + mi * 16) + qrow) * 72 + d0 + qcchunk) * 2;
                ldsm_x4(ah[mi], aaddr);
                ldsm_x4(al[mi], aaddr + FC_AL);
            }
#pragma unroll
            for (int j = 0; j < 8; j++) {
                uint32_t brow = (uint32_t)(wc2 * 64 + 8 * j + (lane & 7));
                uint32_t baddr = base + FC_BH + (brow * 72 + d0 + (lane & 8)) * 2;
                uint32_t bh[2], bl[2];
                ldsm_x2(bh, baddr);
                ldsm_x2(bl, baddr + (FC_BL - FC_BH));
#pragma unroll
                for (int mi = 0; mi < 2; mi++) {
                    mma16816(acc[mi][j], ah[mi], bh);
                    mma16816(acc[mi][j], al[mi], bh);
                    mma16816(acc[mi][j], ah[mi], bl);
                }
            }
        }
        __syncthreads();
    }

#pragma unroll
    for (int mi = 0; mi < 2; mi++) {
        int rA = r0 + wr2 * 32 + mi * 16 + (lane >> 2);
        int rB = rA + 8;
#pragma unroll
        for (int j = 0; j < 8; j++) {
            int o = c0 + wc2 * 64 + 8 * j + ((lane & 3) << 1);
            float b0 = bfc[o], b1 = bfc[o + 1];
            *(float2*)&out[(size_t)rA * E + o] =
                make_float2(acc[mi][j][0] + b0, acc[mi][j][1] + b1);
            *(float2*)&out[(size_t)rB * E + o] =
                make_float2(acc[mi][j][2] + b0, acc[mi][j][3] + b1);
        }
    }
}

// ---------------------------------------------------------------------------

extern "C" void kernel_launch(void* const* d_in, const int* in_sizes, int n_in,
                              void* d_out, int out_size)
{
    const float* x   = (const float*)d_in[0];
    const float* wq  = (const float*)d_in[1];
    const float* bq  = (const float*)d_in[2];
    const float* wk  = (const float*)d_in[3];
    const float* bk  = (const float*)d_in[4];
    const float* wv  = (const float*)d_in[5];
    const float* bv  = (const float*)d_in[6];
    const float* wfc = (const float*)d_in[7];
    const float* bfc = (const float*)d_in[8];
    float* out = (float*)d_out;

    const int conv_smem = (GC * (CTT + 2) + GC * GC * KW + 256 * 33) * 4;

    cudaFuncSetAttribute(conv_qkv_kernel, cudaFuncAttributeMaxDynamicSharedMemorySize, conv_smem);
    cudaFuncSetAttribute(attn_kernel, cudaFuncAttributeMaxDynamicSharedMemorySize, ATT_SMEM);
    cudaFuncSetAttribute(fc_kernel, cudaFuncAttributeMaxDynamicSharedMemorySize, FC_SMEM);

    conv_qkv_kernel<<<dim3(T / CTT, 3 * H, B), 256, conv_smem>>>(x, wq, bq, wk, bk, wv, bv);
    wsplit_kernel<<<E * E / 256, 256>>>(wfc);
    attn_kernel<<<dim3(T / QM, B), 256, ATT_SMEM>>>();
    fc_kernel<<<dim3(E / 128, (B * T) / 128), 256, FC_SMEM>>>(bfc, out);
}

// round 14
// speedup vs baseline: 1.0011x; 1.0011x over previous
#include <cuda_runtime.h>
#include <cuda_fp16.h>
#include <cstdint>

#define B 8
#define E 256
#define T 4096
#define H 8
#define GC 32
#define KW 3
#define CTT 256

// attention tiling
#define QM 64
#define KN 64
#define NT (T / KN)          // 64
#define QSTR 264             // staging stride (halves)
#define KSTR 264             // K row: 256 data (hi only) + 8 pad
#define VSTR 72              // V row: 64 keys + 8 pad
#define PSTR 72

// attn smem byte offsets
#define PH_OFF 0u
#define SL_OFF 9216u
#define KV_OFF 10240u
#define KV_VH 33792u               // K tile bytes (64*528)
#define KVBUF_BYTES 70656u         // K 33792 + Vh 36864
#define ATT_SMEM (KV_OFF + 2u * KVBUF_BYTES)   // 151552

// fc smem
#define FC_AH 0u
#define FC_AL 18432u
#define FC_BH 36864u
#define FC_BL 55296u
#define FC_BUF 73728u
#define FC_SMEM (2u * FC_BUF)   // 147456

// ---------------- device scratch ----------------
__device__ __align__(16) __half g_qh[(size_t)B * T * E];
__device__ __align__(16) __half g_kh[(size_t)B * T * E];     // hi only
__device__ __align__(16) __half g_vh[(size_t)B * E * T];     // [B,d,t]
__device__ __align__(16) __half g_oh[(size_t)B * T * E];
__device__ __align__(16) __half g_ol[(size_t)B * T * E];
__device__ __align__(16) __half g_wh[E * E];
__device__ __align__(16) __half g_wl[E * E];

// ---------------- helpers ----------------
__device__ __forceinline__ uint32_t smem_u32(const void* p) {
    uint32_t a;
    asm("{ .reg .u64 t; cvta.to.shared.u64 t, %1; cvt.u32.u64 %0, t; }" : "=r"(a) : "l"(p));
    return a;
}
__device__ __forceinline__ void ldsm_x4(uint32_t* r, uint32_t a) {
    asm volatile("ldmatrix.sync.aligned.m8n8.x4.shared.b16 {%0,%1,%2,%3}, [%4];"
        : "=r"(r[0]), "=r"(r[1]), "=r"(r[2]), "=r"(r[3]) : "r"(a));
}
__device__ __forceinline__ void ldsm_x2(uint32_t* r, uint32_t a) {
    asm volatile("ldmatrix.sync.aligned.m8n8.x2.shared.b16 {%0,%1}, [%2];"
        : "=r"(r[0]), "=r"(r[1]) : "r"(a));
}
__device__ __forceinline__ void mma16816(float* d, const uint32_t* a, const uint32_t* b) {
    asm volatile("mma.sync.aligned.m16n8k16.row.col.f32.f16.f16.f32 "
        "{%0,%1,%2,%3}, {%4,%5,%6,%7}, {%8,%9}, {%0,%1,%2,%3};"
        : "+f"(d[0]), "+f"(d[1]), "+f"(d[2]), "+f"(d[3])
        : "r"(a[0]), "r"(a[1]), "r"(a[2]), "r"(a[3]), "r"(b[0]), "r"(b[1]));
}
__device__ __forceinline__ void cp16(uint32_t dst, const void* src) {
    asm volatile("cp.async.cg.shared.global [%0], [%1], 16;" :: "r"(dst), "l"(src));
}
#define CP_COMMIT() asm volatile("cp.async.commit_group;" ::: "memory")
#define CP_WAIT1()  asm volatile("cp.async.wait_group 1;" ::: "memory")

__device__ __forceinline__ uint32_t pack_h16(float a, float b) {
    __half2 t = __floats2half2_rn(a, b);
    return *reinterpret_cast<uint32_t*>(&t);
}

// ---------------------------------------------------------------------------
// Kernel 1: grouped conv1d, one projection per block.
// proj 0: q -> fp16 [B,T,E]; proj 1: k -> fp16 [B,T,E];
// proj 2: v -> fp16 transposed [B,E,T].
// ---------------------------------------------------------------------------
__global__ __launch_bounds__(256) void conv_qkv_kernel(
    const float* __restrict__ x,
    const float* __restrict__ wq, const float* __restrict__ bq,
    const float* __restrict__ wk, const float* __restrict__ bk,
    const float* __restrict__ wv, const float* __restrict__ bv)
{
    extern __shared__ float sm[];
    float* sx  = sm;
    float* swT = sx + GC * (CTT + 2);
    float* st  = swT + GC * GC * KW;

    const int tid = threadIdx.x;
    const int b = blockIdx.z;
    const int proj = blockIdx.y / H;
    const int g = blockIdx.y % H;
    const int t0 = blockIdx.x * CTT;

    const float* wsrc = (proj == 0) ? wq : (proj == 1) ? wk : wv;
    const float* bsrc = (proj == 0) ? bq : (proj == 1) ? bk : bv;

    const int gw = g * GC * GC * KW;
    for (int i = tid; i < GC * GC * KW; i += 256) {
        int oc = i & 31, r = i >> 5;
        swT[r * 32 + oc] = wsrc[gw + oc * (GC * KW) + r];
    }
    for (int i = tid; i < GC * (CTT + 2); i += 256) {
        int ic = i / (CTT + 2), tt = i % (CTT + 2);
        int t = t0 + tt - 1;
        sx[i] = (t >= 0 && t < T) ? x[((size_t)b * E + g * GC + ic) * T + t] : 0.f;
    }
    __syncthreads();

    float acc[GC];
#pragma unroll
    for (int oc = 0; oc < GC; oc++) acc[oc] = 0.f;

    const int p = tid;
    for (int ic = 0; ic < GC; ic++) {
        float xk[3];
        xk[0] = sx[ic * (CTT + 2) + p];
        xk[1] = sx[ic * (CTT + 2) + p + 1];
        xk[2] = sx[ic * (CTT + 2) + p + 2];
#pragma unroll
        for (int kw = 0; kw < 3; kw++) {
            const float* wrow = &swT[(ic * 3 + kw) * 32];
#pragma unroll
            for (int oc4 = 0; oc4 < 8; oc4++) {
                float4 w4 = *(const float4*)&wrow[oc4 * 4];
                acc[oc4 * 4 + 0] += xk[kw] * w4.x;
                acc[oc4 * 4 + 1] += xk[kw] * w4.y;
                acc[oc4 * 4 + 2] += xk[kw] * w4.z;
                acc[oc4 * 4 + 3] += xk[kw] * w4.w;
            }
        }
    }

    if (proj == 2) {
#pragma unroll
        for (int oc = 0; oc < GC; oc++) {
            float v = acc[oc] + bsrc[g * GC + oc];
            g_vh[((size_t)b * E + g * GC + oc) * T + t0 + p] = __float2half(v);
        }
        return;
    }

#pragma unroll
    for (int oc = 0; oc < GC; oc++) st[p * 33 + oc] = acc[oc] + bsrc[g * GC + oc];
    __syncthreads();

    __half* dst = (proj == 0) ? g_qh : g_kh;
    const size_t ob = ((size_t)b * T + t0) * E + g * GC;
    for (int i = tid; i < CTT * GC; i += 256) {
        int t = i >> 5, oc = i & 31;
        dst[ob + (size_t)t * E + oc] = __float2half(st[t * 33 + oc]);
    }
}

// ---------------------------------------------------------------------------
// Kernel 1b: split w_fc into fp16 hi/lo
// ---------------------------------------------------------------------------
__global__ void wsplit_kernel(const float* __restrict__ wfc)
{
    int i = blockIdx.x * 256 + threadIdx.x;
    float v = wfc[i];
    __half hi = __float2half(v);
    g_wh[i] = hi;
    g_wl[i] = __float2half(v - __half2float(hi));
}

// ---------------------------------------------------------------------------
// Kernel 2: flash attention. S = Qh*Kh (Q fragments in registers);
// PV = Ph*Vh (single term). No-max softmax. 64-key tiles, double-buffered.
// ---------------------------------------------------------------------------
__device__ __forceinline__ void load_tile_kv(uint32_t sb, int b, int t, int buf, int tid)
{
    const uint32_t base = sb + KV_OFF + (uint32_t)buf * KVBUF_BYTES;
    const char* ksrc = (const char*)(g_kh + ((size_t)(b * T + t * KN)) * E);
    for (int i = tid; i < 2048; i += 256) {
        int key = i >> 5, c = i & 31;
        cp16(base + key * 528 + c * 16, ksrc + (size_t)key * 512 + c * 16);
    }
    const char* vhsrc = (const char*)(g_vh + (size_t)b * E * T + (size_t)t * KN);
    for (int i = tid; i < 2048; i += 256) {
        int d = i >> 3, c = i & 7;
        cp16(base + KV_VH + d * 144 + c * 16, vhsrc + (size_t)d * T * 2 + c * 16);
    }
    CP_COMMIT();
}

__global__ __launch_bounds__(256, 1) void attn_kernel()
{
    extern __shared__ char smem[];
    const uint32_t sb = smem_u32(smem);
    float* sL = (float*)(smem + SL_OFF);     // [2][64]

    const int tid = threadIdx.x;
    const int wid = tid >> 5, lane = tid & 31;
    const int b = blockIdx.y;
    const int q0 = blockIdx.x * QM;
    const float scale = 0.0625f;

    // S grid: warp = 16 rows x 32 cols. PV grid: warp = 32 rows x 64 d.
    const int r0 = (wid >> 1) * 16, c0 = (wid & 1) * 32;
    const int rr0 = (wid >> 2) * 32, dd0 = (wid & 3) * 64;

    const uint32_t qrow = (uint32_t)(lane & 15);
    const uint32_t qcchunk = (uint32_t)((lane >> 4) << 3);
    const uint32_t brow8 = (uint32_t)((lane & 7) + ((lane >> 4) << 3));
    const uint32_t bcol8 = (uint32_t)(lane & 8);

    // ---- stage Q into KV area, ldmatrix into registers, then release ----
    uint32_t qf[16][4];
    {
        for (int i = tid; i < 2048; i += 256) {
            int r = i >> 5, c8 = i & 31;
            *(uint4*)(smem + KV_OFF + r * (QSTR * 2) + c8 * 16) =
                *(const uint4*)((const char*)(g_qh + ((size_t)(b * T + q0 + r)) * E) + c8 * 16);
        }
        __syncthreads();
#pragma unroll
        for (int kk = 0; kk < 16; kk++)
            ldsm_x4(qf[kk], sb + KV_OFF +
                    (((uint32_t)r0 + qrow) * QSTR + kk * 16 + qcchunk) * 2);
        __syncthreads();
    }

    load_tile_kv(sb, b, 0, 0, tid);

    float oacc[2][8][4];
#pragma unroll
    for (int mi = 0; mi < 2; mi++)
#pragma unroll
        for (int j = 0; j < 8; j++)
#pragma unroll
            for (int e = 0; e < 4; e++) oacc[mi][j][e] = 0.f;
    float lsum[2] = {0.f, 0.f};

    for (int t = 0; t < NT; t++) {
        if (t + 1 < NT) load_tile_kv(sb, b, t + 1, (t + 1) & 1, tid);
        else CP_COMMIT();
        CP_WAIT1();
        __syncthreads();

        const uint32_t kb = sb + KV_OFF + (uint32_t)(t & 1) * KVBUF_BYTES;

        // ---- S = Qh*Kh ----
        float sacc[4][4];
#pragma unroll
        for (int j = 0; j < 4; j++)
#pragma unroll
            for (int e = 0; e < 4; e++) sacc[j][e] = 0.f;

#pragma unroll
        for (int kk = 0; kk < 16; kk++) {
            const int d0 = kk * 16;
#pragma unroll
            for (int jp = 0; jp < 2; jp++) {
                uint32_t key = (uint32_t)(c0 + 16 * jp) + brow8;
                uint32_t bb[4];
                ldsm_x4(bb, kb + (key * KSTR + d0 + bcol8) * 2);
                mma16816(sacc[2 * jp],     qf[kk], bb);
                mma16816(sacc[2 * jp + 1], qf[kk], bb + 2);
            }
        }

        // ---- P = exp(S*scale); l; store Ph -> smem ----
#pragma unroll
        for (int j = 0; j < 4; j++) {
            float p0 = __expf(sacc[j][0] * scale);
            float p1 = __expf(sacc[j][1] * scale);
            float p2 = __expf(sacc[j][2] * scale);
            float p3 = __expf(sacc[j][3] * scale);
            lsum[0] += p0 + p1;
            lsum[1] += p2 + p3;
            int row = r0 + (lane >> 2);
            int col = c0 + 8 * j + ((lane & 3) << 1);
            *(uint32_t*)(smem + PH_OFF + row * (PSTR * 2) + col * 2) = pack_h16(p0, p1);
            *(uint32_t*)(smem + PH_OFF + (row + 8) * (PSTR * 2) + col * 2) = pack_h16(p2, p3);
        }
        __syncthreads();

        // ---- O += Ph*Vh ----
#pragma unroll
        for (int kk2 = 0; kk2 < 4; kk2++) {
            const int key0 = kk2 * 16;
            uint32_t ph[2][4];
#pragma unroll
            for (int mi = 0; mi < 2; mi++) {
                uint32_t prow = (uint32_t)(rr0 + 16 * mi) + qrow;
                ldsm_x4(ph[mi], sb + PH_OFF + (prow * PSTR + key0 + qcchunk) * 2);
            }
#pragma unroll
            for (int jp = 0; jp < 4; jp++) {
                uint32_t drow = (uint32_t)(dd0 + 16 * jp) + brow8;
                uint32_t bb[4];
                ldsm_x4(bb, kb + KV_VH + (drow * VSTR + key0 + bcol8) * 2);
#pragma unroll
                for (int mi = 0; mi < 2; mi++) {
                    mma16816(oacc[mi][2 * jp],     ph[mi], bb);
                    mma16816(oacc[mi][2 * jp + 1], ph[mi], bb + 2);
                }
            }
        }
        __syncthreads();
    }

    // ---- l reduction ----
    lsum[0] += __shfl_xor_sync(0xffffffffu, lsum[0], 1);
    lsum[0] += __shfl_xor_sync(0xffffffffu, lsum[0], 2);
    lsum[1] += __shfl_xor_sync(0xffffffffu, lsum[1], 1);
    lsum[1] += __shfl_xor_sync(0xffffffffu, lsum[1], 2);
    if ((lane & 3) == 0) {
        sL[(wid & 1) * 64 + r0 + (lane >> 2)] = lsum[0];
        sL[(wid & 1) * 64 + r0 + 8 + (lane >> 2)] = lsum[1];
    }
    __syncthreads();

    // ---- O /= l, write fp16 hi/lo ----
#pragma unroll
    for (int mi = 0; mi < 2; mi++) {
        int rA = rr0 + 16 * mi + (lane >> 2);
        int rB = rA + 8;
        float invA = 1.f / (sL[rA] + sL[64 + rA]);
        float invB = 1.f / (sL[rB] + sL[64 + rB]);
        size_t oa = ((size_t)(b * T + q0 + rA)) * E;
        size_t ob = ((size_t)(b * T + q0 + rB)) * E;
#pragma unroll
        for (int j = 0; j < 8; j++) {
            int col = dd0 + 8 * j + ((lane & 3) << 1);
            float a0 = oacc[mi][j][0] * invA, a1 = oacc[mi][j][1] * invA;
            float b0 = oacc[mi][j][2] * invB, b1 = oacc[mi][j][3] * invB;
            __half ha0 = __float2half(a0), ha1 = __float2half(a1);
            __half hb0 = __float2half(b0), hb1 = __float2half(b1);
            *(uint32_t*)(g_oh + oa + col) = pack_h16(a0, a1);
            *(uint32_t*)(g_ol + oa + col) =
                pack_h16(a0 - __half2float(ha0), a1 - __half2float(ha1));
            *(uint32_t*)(g_oh + ob + col) = pack_h16(b0, b1);
            *(uint32_t*)(g_ol + ob + col) =
                pack_h16(b0 - __half2float(hb0), b1 - __half2float(hb1));
        }
    }
}

// ---------------------------------------------------------------------------
// Kernel 3: fc_out via fp16 mma 3-term. CTA 128r x 128c, K=256 in 4 chunks.
// ---------------------------------------------------------------------------
__device__ __forceinline__ void load_fc(uint32_t sb, int r0, int c0, int c, int buf, int tid)
{
    const uint32_t base = sb + (uint32_t)buf * FC_BUF;
    for (int i = tid; i < 1024; i += 256) {
        int row = i >> 3, seg = i & 7;
        const size_t ao = (size_t)(r0 + row) * E + c * 64;
        const size_t bo = (size_t)(c0 + row) * E + c * 64;
        cp16(base + FC_AH + row * 144 + seg * 16, (const char*)(g_oh + ao) + seg * 16);
        cp16(base + FC_AL + row * 144 + seg * 16, (const char*)(g_ol + ao) + seg * 16);
        cp16(base + FC_BH + row * 144 + seg * 16, (const char*)(g_wh + bo) + seg * 16);
        cp16(base + FC_BL + row * 144 + seg * 16, (const char*)(g_wl + bo) + seg * 16);
    }
    CP_COMMIT();
}

__global__ __launch_bounds__(256, 1) void fc_kernel(
    const float* __restrict__ bfc, float* __restrict__ out)
{
    extern __shared__ char smem[];
    const uint32_t sb = smem_u32(smem);

    const int tid = threadIdx.x;
    const int wid = tid >> 5, lane = tid & 31;
    const int r0 = blockIdx.y * 128, c0 = blockIdx.x * 128;
    const int wr2 = wid >> 1, wc2 = wid & 1;

    float acc[2][8][4];
#pragma unroll
    for (int mi = 0; mi < 2; mi++)
#pragma unroll
        for (int j = 0; j < 8; j++)
#pragma unroll
            for (int e = 0; e < 4; e++) acc[mi][j][e] = 0.f;

    const uint32_t qrow = (uint32_t)(lane & 15);
    const uint32_t qcchunk = (uint32_t)((lane >> 4) << 3);

    load_fc(sb, r0, c0, 0, 0, tid);

    for (int c = 0; c < 4; c++) {
        if (c + 1 < 4) load_fc(sb, r0, c0, c + 1, (c + 1) & 1, tid);
        else CP_COMMIT();
        CP_WAIT1();
        __syncthreads();
        const uint32_t base = sb + (uint32_t)(c & 1) * FC_BUF;

#pragma unroll
        for (int kk = 0; kk < 4; kk++) {
            const int d0 = kk * 16;
            uint32_t ah[2][4], al[2][4];
#pragma unroll
            for (int mi = 0; mi < 2; mi++) {
                uint32_t aaddr = base + FC_AH +
                    (((uint32_t)(wr2 * 32 + mi * 16) + qrow) * 72 + d0 + qcchunk) * 2;
                ldsm_x4(ah[mi], aaddr);
                ldsm_x4(al[mi], aaddr + FC_AL);
            }
#pragma unroll
            for (int j = 0; j < 8; j++) {
                uint32_t brow = (uint32_t)(wc2 * 64 + 8 * j + (lane & 7));
                uint32_t baddr = base + FC_BH + (brow * 72 + d0 + (lane & 8)) * 2;
                uint32_t bh[2], bl[2];
                ldsm_x2(bh, baddr);
                ldsm_x2(bl, baddr + (FC_BL - FC_BH));
#pragma unroll
                for (int mi = 0; mi < 2; mi++) {
                    mma16816(acc[mi][j], ah[mi], bh);
                    mma16816(acc[mi][j], al[mi], bh);
                    mma16816(acc[mi][j], ah[mi], bl);
                }
            }
        }
        __syncthreads();
    }

#pragma unroll
    for (int mi = 0; mi < 2; mi++) {
        int rA = r0 + wr2 * 32 + mi * 16 + (lane >> 2);
        int rB = rA + 8;
#pragma unroll
        for (int j = 0; j < 8; j++) {
            int o = c0 + wc2 * 64 + 8 * j + ((lane & 3) << 1);
            float b0 = bfc[o], b1 = bfc[o + 1];
            *(float2*)&out[(size_t)rA * E + o] =
                make_float2(acc[mi][j][0] + b0, acc[mi][j][1] + b1);
            *(float2*)&out[(size_t)rB * E + o] =
                make_float2(acc[mi][j][2] + b0, acc[mi][j][3] + b1);
        }
    }
}

// ---------------------------------------------------------------------------

extern "C" void kernel_launch(void* const* d_in, const int* in_sizes, int n_in,
                              void* d_out, int out_size)
{
    const float* x   = (const float*)d_in[0];
    const float* wq  = (const float*)d_in[1];
    const float* bq  = (const float*)d_in[2];
    const float* wk  = (const float*)d_in[3];
    const float* bk  = (const float*)d_in[4];
    const float* wv  = (const float*)d_in[5];
    const float* bv  = (const float*)d_in[6];
    const float* wfc = (const float*)d_in[7];
    const float* bfc = (const float*)d_in[8];
    float* out = (float*)d_out;

    const int conv_smem = (GC * (CTT + 2) + GC * GC * KW + 256 * 33) * 4;

    cudaFuncSetAttribute(conv_qkv_kernel, cudaFuncAttributeMaxDynamicSharedMemorySize, conv_smem);
    cudaFuncSetAttribute(attn_kernel, cudaFuncAttributeMaxDynamicSharedMemorySize, ATT_SMEM);
    cudaFuncSetAttribute(fc_kernel, cudaFuncAttributeMaxDynamicSharedMemorySize, FC_SMEM);

    conv_qkv_kernel<<<dim3(T / CTT, 3 * H, B), 256, conv_smem>>>(x, wq, bq, wk, bk, wv, bv);
    wsplit_kernel<<<E * E / 256, 256>>>(wfc);
    attn_kernel<<<dim3(T / QM, B), 256, ATT_SMEM>>>();
    fc_kernel<<<dim3(E / 128, (B * T) / 128), 256, FC_SMEM>>>(bfc, out);
}

// round 16
// speedup vs baseline: 1.0305x; 1.0293x over previous
#include <cuda_runtime.h>
#include <cuda_fp16.h>
#include <cstdint>

#define B 8
#define E 256
#define T 4096
#define H 8
#define GC 32
#define KW 3
#define CTT 256

// attention tiling
#define QM 64
#define KN 64
#define NT (T / KN)          // 64
#define QSTR 264             // staging stride (halves)
#define KSTR 264             // K row: 256 data + 8 pad
#define VSTR 72              // V row: 64 keys + 8 pad
#define PSTR 72

// attn smem byte offsets
#define PH0_OFF 0u
#define PH1_OFF 9216u
#define SL_OFF 18432u
#define KV_OFF 19456u
#define KV_VH 33792u               // K tile bytes (64*528)
#define KVBUF_BYTES 70656u         // K 33792 + Vh 36864
#define ATT_SMEM (KV_OFF + 3u * KVBUF_BYTES)   // 231424

// fc smem
#define FC_AH 0u
#define FC_AL 18432u
#define FC_BH 36864u
#define FC_BL 55296u
#define FC_BUF 73728u
#define FC_SMEM (2u * FC_BUF)   // 147456

// ---------------- device scratch ----------------
__device__ __align__(16) __half g_qh[(size_t)B * T * E];
__device__ __align__(16) __half g_kh[(size_t)B * T * E];
__device__ __align__(16) __half g_vh[(size_t)B * E * T];     // [B,d,t]
__device__ __align__(16) __half g_oh[(size_t)B * T * E];
__device__ __align__(16) __half g_ol[(size_t)B * T * E];
__device__ __align__(16) __half g_wh[E * E];
__device__ __align__(16) __half g_wl[E * E];

// ---------------- helpers ----------------
__device__ __forceinline__ uint32_t smem_u32(const void* p) {
    uint32_t a;
    asm("{ .reg .u64 t; cvta.to.shared.u64 t, %1; cvt.u32.u64 %0, t; }" : "=r"(a) : "l"(p));
    return a;
}
__device__ __forceinline__ void ldsm_x4(uint32_t* r, uint32_t a) {
    asm volatile("ldmatrix.sync.aligned.m8n8.x4.shared.b16 {%0,%1,%2,%3}, [%4];"
        : "=r"(r[0]), "=r"(r[1]), "=r"(r[2]), "=r"(r[3]) : "r"(a));
}
__device__ __forceinline__ void ldsm_x2(uint32_t* r, uint32_t a) {
    asm volatile("ldmatrix.sync.aligned.m8n8.x2.shared.b16 {%0,%1}, [%2];"
        : "=r"(r[0]), "=r"(r[1]) : "r"(a));
}
__device__ __forceinline__ void mma16816(float* d, const uint32_t* a, const uint32_t* b) {
    asm volatile("mma.sync.aligned.m16n8k16.row.col.f32.f16.f16.f32 "
        "{%0,%1,%2,%3}, {%4,%5,%6,%7}, {%8,%9}, {%0,%1,%2,%3};"
        : "+f"(d[0]), "+f"(d[1]), "+f"(d[2]), "+f"(d[3])
        : "r"(a[0]), "r"(a[1]), "r"(a[2]), "r"(a[3]), "r"(b[0]), "r"(b[1]));
}
__device__ __forceinline__ void cp16(uint32_t dst, const void* src) {
    asm volatile("cp.async.cg.shared.global [%0], [%1], 16;" :: "r"(dst), "l"(src));
}
#define CP_COMMIT()   asm volatile("cp.async.commit_group;" ::: "memory")
#define CP_WAIT1()    asm volatile("cp.async.wait_group 1;" ::: "memory")
#define CP_WAIT_ALL() asm volatile("cp.async.wait_group 0;" ::: "memory")

__device__ __forceinline__ uint32_t pack_h16(float a, float b) {
    __half2 t = __floats2half2_rn(a, b);
    return *reinterpret_cast<uint32_t*>(&t);
}

// ---------------------------------------------------------------------------
// Kernel 1: grouped conv1d, one projection per block.
// ---------------------------------------------------------------------------
__global__ __launch_bounds__(256) void conv_qkv_kernel(
    const float* __restrict__ x,
    const float* __restrict__ wq, const float* __restrict__ bq,
    const float* __restrict__ wk, const float* __restrict__ bk,
    const float* __restrict__ wv, const float* __restrict__ bv)
{
    extern __shared__ float sm[];
    float* sx  = sm;
    float* swT = sx + GC * (CTT + 2);
    float* st  = swT + GC * GC * KW;

    const int tid = threadIdx.x;
    const int b = blockIdx.z;
    const int proj = blockIdx.y / H;
    const int g = blockIdx.y % H;
    const int t0 = blockIdx.x * CTT;

    const float* wsrc = (proj == 0) ? wq : (proj == 1) ? wk : wv;
    const float* bsrc = (proj == 0) ? bq : (proj == 1) ? bk : bv;

    const int gw = g * GC * GC * KW;
    for (int i = tid; i < GC * GC * KW; i += 256) {
        int oc = i & 31, r = i >> 5;
        swT[r * 32 + oc] = wsrc[gw + oc * (GC * KW) + r];
    }
    for (int i = tid; i < GC * (CTT + 2); i += 256) {
        int ic = i / (CTT + 2), tt = i % (CTT + 2);
        int t = t0 + tt - 1;
        sx[i] = (t >= 0 && t < T) ? x[((size_t)b * E + g * GC + ic) * T + t] : 0.f;
    }
    __syncthreads();

    float acc[GC];
#pragma unroll
    for (int oc = 0; oc < GC; oc++) acc[oc] = 0.f;

    const int p = tid;
    for (int ic = 0; ic < GC; ic++) {
        float xk[3];
        xk[0] = sx[ic * (CTT + 2) + p];
        xk[1] = sx[ic * (CTT + 2) + p + 1];
        xk[2] = sx[ic * (CTT + 2) + p + 2];
#pragma unroll
        for (int kw = 0; kw < 3; kw++) {
            const float* wrow = &swT[(ic * 3 + kw) * 32];
#pragma unroll
            for (int oc4 = 0; oc4 < 8; oc4++) {
                float4 w4 = *(const float4*)&wrow[oc4 * 4];
                acc[oc4 * 4 + 0] += xk[kw] * w4.x;
                acc[oc4 * 4 + 1] += xk[kw] * w4.y;
                acc[oc4 * 4 + 2] += xk[kw] * w4.z;
                acc[oc4 * 4 + 3] += xk[kw] * w4.w;
            }
        }
    }

    if (proj == 2) {
#pragma unroll
        for (int oc = 0; oc < GC; oc++) {
            float v = acc[oc] + bsrc[g * GC + oc];
            g_vh[((size_t)b * E + g * GC + oc) * T + t0 + p] = __float2half(v);
        }
        return;
    }

#pragma unroll
    for (int oc = 0; oc < GC; oc++) st[p * 33 + oc] = acc[oc] + bsrc[g * GC + oc];
    __syncthreads();

    __half* dst = (proj == 0) ? g_qh : g_kh;
    const size_t ob = ((size_t)b * T + t0) * E + g * GC;
    for (int i = tid; i < CTT * GC; i += 256) {
        int t = i >> 5, oc = i & 31;
        dst[ob + (size_t)t * E + oc] = __float2half(st[t * 33 + oc]);
    }
}

// ---------------------------------------------------------------------------
// Kernel 1b: split w_fc into fp16 hi/lo
// ---------------------------------------------------------------------------
__global__ void wsplit_kernel(const float* __restrict__ wfc)
{
    int i = blockIdx.x * 256 + threadIdx.x;
    float v = wfc[i];
    __half hi = __float2half(v);
    g_wh[i] = hi;
    g_wl[i] = __float2half(v - __half2float(hi));
}

// ---------------------------------------------------------------------------
// Kernel 2: flash attention, skewed pipeline:
//   iter t: exp(S(t)) -> P | wait+sync | [ PV(t) + S(t+1) ] one fused mma block.
// 3 KV buffers, double-buffered P, one sync per tile.
// ---------------------------------------------------------------------------
__device__ __forceinline__ void load_tile_kv(uint32_t sb, int b, int t, int buf, int tid)
{
    const uint32_t base = sb + KV_OFF + (uint32_t)buf * KVBUF_BYTES;
    const char* ksrc = (const char*)(g_kh + ((size_t)(b * T + t * KN)) * E);
    for (int i = tid; i < 2048; i += 256) {
        int key = i >> 5, c = i & 31;
        cp16(base + key * 528 + c * 16, ksrc + (size_t)key * 512 + c * 16);
    }
    const char* vhsrc = (const char*)(g_vh + (size_t)b * E * T + (size_t)t * KN);
    for (int i = tid; i < 2048; i += 256) {
        int d = i >> 3, c = i & 7;
        cp16(base + KV_VH + d * 144 + c * 16, vhsrc + (size_t)d * T * 2 + c * 16);
    }
    CP_COMMIT();
}

__global__ __launch_bounds__(256, 1) void attn_kernel()
{
    extern __shared__ char smem[];
    const uint32_t sb = smem_u32(smem);
    float* sL = (float*)(smem + SL_OFF);     // [2][64]

    const int tid = threadIdx.x;
    const int wid = tid >> 5, lane = tid & 31;
    const int b = blockIdx.y;
    const int q0 = blockIdx.x * QM;
    const float scale = 0.0625f;

    // S grid: warp = 16 rows x 32 cols. PV grid: warp = 32 rows x 64 d.
    const int r0 = (wid >> 1) * 16, c0 = (wid & 1) * 32;
    const int rr0 = (wid >> 2) * 32, dd0 = (wid & 3) * 64;

    const uint32_t qrow = (uint32_t)(lane & 15);
    const uint32_t qcchunk = (uint32_t)((lane >> 4) << 3);
    const uint32_t brow8 = (uint32_t)((lane & 7) + ((lane >> 4) << 3));
    const uint32_t bcol8 = (uint32_t)(lane & 8);

    // ---- stage Q into KV area, ldmatrix into registers, then release ----
    uint32_t qf[16][4];
    {
        for (int i = tid; i < 2048; i += 256) {
            int r = i >> 5, c8 = i & 31;
            *(uint4*)(smem + KV_OFF + r * (QSTR * 2) + c8 * 16) =
                *(const uint4*)((const char*)(g_qh + ((size_t)(b * T + q0 + r)) * E) + c8 * 16);
        }
        __syncthreads();
#pragma unroll
        for (int kk = 0; kk < 16; kk++)
            ldsm_x4(qf[kk], sb + KV_OFF +
                    (((uint32_t)r0 + qrow) * QSTR + kk * 16 + qcchunk) * 2);
        __syncthreads();
    }

    load_tile_kv(sb, b, 0, 0, tid);
    load_tile_kv(sb, b, 1, 1, tid);

    float oacc[2][8][4];
#pragma unroll
    for (int mi = 0; mi < 2; mi++)
#pragma unroll
        for (int j = 0; j < 8; j++)
#pragma unroll
            for (int e = 0; e < 4; e++) oacc[mi][j][e] = 0.f;
    float lsum[2] = {0.f, 0.f};
    float sacc[4][4];

    // ---- preamble: S(0) ----
    CP_WAIT1();
    __syncthreads();
#pragma unroll
    for (int j = 0; j < 4; j++)
#pragma unroll
        for (int e = 0; e < 4; e++) sacc[j][e] = 0.f;
    {
        const uint32_t kb = sb + KV_OFF;   // buf 0
#pragma unroll
        for (int kk = 0; kk < 16; kk++) {
            const int d0 = kk * 16;
#pragma unroll
            for (int jp = 0; jp < 2; jp++) {
                uint32_t key = (uint32_t)(c0 + 16 * jp) + brow8;
                uint32_t bb[4];
                ldsm_x4(bb, kb + (key * KSTR + d0 + bcol8) * 2);
                mma16816(sacc[2 * jp],     qf[kk], bb);
                mma16816(sacc[2 * jp + 1], qf[kk], bb + 2);
            }
        }
    }

    int bufv = 0, bufk = 1, bufl = 2;   // buffers for V(t), K(t+1), load(t+2)
    for (int t = 0; t < NT; t++) {
        // ---- exp(S(t)) -> P[t&1]; l ----  (stores via GENERIC pointer)
        char* php = smem + ((t & 1) ? PH1_OFF : PH0_OFF);
        const uint32_t phs = sb + ((t & 1) ? PH1_OFF : PH0_OFF);
#pragma unroll
        for (int j = 0; j < 4; j++) {
            float p0 = __expf(sacc[j][0] * scale);
            float p1 = __expf(sacc[j][1] * scale);
            float p2 = __expf(sacc[j][2] * scale);
            float p3 = __expf(sacc[j][3] * scale);
            lsum[0] += p0 + p1;
            lsum[1] += p2 + p3;
            int row = r0 + (lane >> 2);
            int col = c0 + 8 * j + ((lane & 3) << 1);
            *(uint32_t*)(php + row * (PSTR * 2) + col * 2) = pack_h16(p0, p1);
            *(uint32_t*)(php + (row + 8) * (PSTR * 2) + col * 2) = pack_h16(p2, p3);
        }

        CP_WAIT_ALL();        // K(t+1)+V(t+1) resident
        __syncthreads();      // P visible; all warps past previous mma block
        if (t + 2 < NT) load_tile_kv(sb, b, t + 2, bufl, tid);

        const uint32_t vb = sb + KV_OFF + (uint32_t)bufv * KVBUF_BYTES + KV_VH;

        // ---- PV(t): O += Ph*Vh ----
#pragma unroll
        for (int kk2 = 0; kk2 < 4; kk2++) {
            const int key0 = kk2 * 16;
            uint32_t ph2[2][4];
#pragma unroll
            for (int mi = 0; mi < 2; mi++) {
                uint32_t prow = (uint32_t)(rr0 + 16 * mi) + qrow;
                ldsm_x4(ph2[mi], phs + (prow * PSTR + key0 + qcchunk) * 2);
            }
#pragma unroll
            for (int jp = 0; jp < 4; jp++) {
                uint32_t drow = (uint32_t)(dd0 + 16 * jp) + brow8;
                uint32_t bb[4];
                ldsm_x4(bb, vb + (drow * VSTR + key0 + bcol8) * 2);
#pragma unroll
                for (int mi = 0; mi < 2; mi++) {
                    mma16816(oacc[mi][2 * jp],     ph2[mi], bb);
                    mma16816(oacc[mi][2 * jp + 1], ph2[mi], bb + 2);
                }
            }
        }

        // ---- S(t+1) ----
        if (t + 1 < NT) {
            const uint32_t kb = sb + KV_OFF + (uint32_t)bufk * KVBUF_BYTES;
#pragma unroll
            for (int j = 0; j < 4; j++)
#pragma unroll
                for (int e = 0; e < 4; e++) sacc[j][e] = 0.f;
#pragma unroll
            for (int kk = 0; kk < 16; kk++) {
                const int d0 = kk * 16;
#pragma unroll
                for (int jp = 0; jp < 2; jp++) {
                    uint32_t key = (uint32_t)(c0 + 16 * jp) + brow8;
                    uint32_t bb[4];
                    ldsm_x4(bb, kb + (key * KSTR + d0 + bcol8) * 2);
                    mma16816(sacc[2 * jp],     qf[kk], bb);
                    mma16816(sacc[2 * jp + 1], qf[kk], bb + 2);
                }
            }
        }

        // rotate buffers
        int tmp = bufv; bufv = bufk; bufk = bufl; bufl = tmp;
    }

    // ---- l reduction ----
    lsum[0] += __shfl_xor_sync(0xffffffffu, lsum[0], 1);
    lsum[0] += __shfl_xor_sync(0xffffffffu, lsum[0], 2);
    lsum[1] += __shfl_xor_sync(0xffffffffu, lsum[1], 1);
    lsum[1] += __shfl_xor_sync(0xffffffffu, lsum[1], 2);
    __syncthreads();
    if ((lane & 3) == 0) {
        sL[(wid & 1) * 64 + r0 + (lane >> 2)] = lsum[0];
        sL[(wid & 1) * 64 + r0 + 8 + (lane >> 2)] = lsum[1];
    }
    __syncthreads();

    // ---- O /= l, write fp16 hi/lo ----
#pragma unroll
    for (int mi = 0; mi < 2; mi++) {
        int rA = rr0 + 16 * mi + (lane >> 2);
        int rB = rA + 8;
        float invA = 1.f / (sL[rA] + sL[64 + rA]);
        float invB = 1.f / (sL[rB] + sL[64 + rB]);
        size_t oa = ((size_t)(b * T + q0 + rA)) * E;
        size_t ob = ((size_t)(b * T + q0 + rB)) * E;
#pragma unroll
        for (int j = 0; j < 8; j++) {
            int col = dd0 + 8 * j + ((lane & 3) << 1);
            float a0 = oacc[mi][j][0] * invA, a1 = oacc[mi][j][1] * invA;
            float b0 = oacc[mi][j][2] * invB, b1 = oacc[mi][j][3] * invB;
            __half ha0 = __float2half(a0), ha1 = __float2half(a1);
            __half hb0 = __float2half(b0), hb1 = __float2half(b1);
            *(uint32_t*)(g_oh + oa + col) = pack_h16(a0, a1);
            *(uint32_t*)(g_ol + oa + col) =
                pack_h16(a0 - __half2float(ha0), a1 - __half2float(ha1));
            *(uint32_t*)(g_oh + ob + col) = pack_h16(b0, b1);
            *(uint32_t*)(g_ol + ob + col) =
                pack_h16(b0 - __half2float(hb0), b1 - __half2float(hb1));
        }
    }
}

// ---------------------------------------------------------------------------
// Kernel 3: fc_out via fp16 mma 3-term. CTA 128r x 128c, K=256 in 4 chunks.
// ---------------------------------------------------------------------------
__device__ __forceinline__ void load_fc(uint32_t sb, int r0, int c0, int c, int buf, int tid)
{
    const uint32_t base = sb + (uint32_t)buf * FC_BUF;
    for (int i = tid; i < 1024; i += 256) {
        int row = i >> 3, seg = i & 7;
        const size_t ao = (size_t)(r0 + row) * E + c * 64;
        const size_t bo = (size_t)(c0 + row) * E + c * 64;
        cp16(base + FC_AH + row * 144 + seg * 16, (const char*)(g_oh + ao) + seg * 16);
        cp16(base + FC_AL + row * 144 + seg * 16, (const char*)(g_ol + ao) + seg * 16);
        cp16(base + FC_BH + row * 144 + seg * 16, (const char*)(g_wh + bo) + seg * 16);
        cp16(base + FC_BL + row * 144 + seg * 16, (const char*)(g_wl + bo) + seg * 16);
    }
    CP_COMMIT();
}

__global__ __launch_bounds__(256, 1) void fc_kernel(
    const float* __restrict__ bfc, float* __restrict__ out)
{
    extern __shared__ char smem[];
    const uint32_t sb = smem_u32(smem);

    const int tid = threadIdx.x;
    const int wid = tid >> 5, lane = tid & 31;
    const int r0 = blockIdx.y * 128, c0 = blockIdx.x * 128;
    const int wr2 = wid >> 1, wc2 = wid & 1;

    float acc[2][8][4];
#pragma unroll
    for (int mi = 0; mi < 2; mi++)
#pragma unroll
        for (int j = 0; j < 8; j++)
#pragma unroll
            for (int e = 0; e < 4; e++) acc[mi][j][e] = 0.f;

    const uint32_t qrow = (uint32_t)(lane & 15);
    const uint32_t qcchunk = (uint32_t)((lane >> 4) << 3);

    load_fc(sb, r0, c0, 0, 0, tid);

    for (int c = 0; c < 4; c++) {
        if (c + 1 < 4) load_fc(sb, r0, c0, c + 1, (c + 1) & 1, tid);
        else CP_COMMIT();
        CP_WAIT1();
        __syncthreads();
        const uint32_t base = sb + (uint32_t)(c & 1) * FC_BUF;

#pragma unroll
        for (int kk = 0; kk < 4; kk++) {
            const int d0 = kk * 16;
            uint32_t ah[2][4], al[2][4];
#pragma unroll
            for (int mi = 0; mi < 2; mi++) {
                uint32_t aaddr = base + FC_AH +
                    (((uint32_t)(wr2 * 32 + mi * 16) + qrow) * 72 + d0 + qcchunk) * 2;
                ldsm_x4(ah[mi], aaddr);
                ldsm_x4(al[mi], aaddr + FC_AL);
            }
#pragma unroll
            for (int j = 0; j < 8; j++) {
                uint32_t brow = (uint32_t)(wc2 * 64 + 8 * j + (lane & 7));
                uint32_t baddr = base + FC_BH + (brow * 72 + d0 + (lane & 8)) * 2;
                uint32_t bh[2], bl[2];
                ldsm_x2(bh, baddr);
                ldsm_x2(bl, baddr + (FC_BL - FC_BH));
#pragma unroll
                for (int mi = 0; mi < 2; mi++) {
                    mma16816(acc[mi][j], ah[mi], bh);
                    mma16816(acc[mi][j], al[mi], bh);
                    mma16816(acc[mi][j], ah[mi], bl);
                }
            }
        }
        __syncthreads();
    }

#pragma unroll
    for (int mi = 0; mi < 2; mi++) {
        int rA = r0 + wr2 * 32 + mi * 16 + (lane >> 2);
        int rB = rA + 8;
#pragma unroll
        for (int j = 0; j < 8; j++) {
            int o = c0 + wc2 * 64 + 8 * j + ((lane & 3) << 1);
            float b0 = bfc[o], b1 = bfc[o + 1];
            *(float2*)&out[(size_t)rA * E + o] =
                make_float2(acc[mi][j][0] + b0, acc[mi][j][1] + b1);
            *(float2*)&out[(size_t)rB * E + o] =
                make_float2(acc[mi][j][2] + b0, acc[mi][j][3] + b1);
        }
    }
}

// ---------------------------------------------------------------------------

extern "C" void kernel_launch(void* const* d_in, const int* in_sizes, int n_in,
                              void* d_out, int out_size)
{
    const float* x   = (const float*)d_in[0];
    const float* wq  = (const float*)d_in[1];
    const float* bq  = (const float*)d_in[2];
    const float* wk  = (const float*)d_in[3];
    const float* bk  = (const float*)d_in[4];
    const float* wv  = (const float*)d_in[5];
    const float* bv  = (const float*)d_in[6];
    const float* wfc = (const float*)d_in[7];
    const float* bfc = (const float*)d_in[8];
    float* out = (float*)d_out;

    const int conv_smem = (GC * (CTT + 2) + GC * GC * KW + 256 * 33) * 4;

    cudaFuncSetAttribute(conv_qkv_kernel, cudaFuncAttributeMaxDynamicSharedMemorySize, conv_smem);
    cudaFuncSetAttribute(attn_kernel, cudaFuncAttributeMaxDynamicSharedMemorySize, ATT_SMEM);
    cudaFuncSetAttribute(fc_kernel, cudaFuncAttributeMaxDynamicSharedMemorySize, FC_SMEM);

    conv_qkv_kernel<<<dim3(T / CTT, 3 * H, B), 256, conv_smem>>>(x, wq, bq, wk, bk, wv, bv);
    wsplit_kernel<<<E * E / 256, 256>>>(wfc);
    attn_kernel<<<dim3(T / QM, B), 256, ATT_SMEM>>>();
    fc_kernel<<<dim3(E / 128, (B * T) / 128), 256, FC_SMEM>>>(bfc, out);
}

// round 17
// speedup vs baseline: 1.0759x; 1.0441x over previous
#include <cuda_runtime.h>
#include <cuda_fp16.h>
#include <cstdint>

#define B 8
#define E 256
#define T 4096
#define H 8
#define GC 32
#define KW 3
#define CTT 256

// attention tiling
#define QM 64
#define KN 64
#define NT (T / KN)          // 64
#define QSTR 264             // staging stride (halves)
#define KSTR 264             // K row: 256 data + 8 pad
#define VSTR 72              // V row: 64 keys + 8 pad
#define PSTR 72

// attn smem byte offsets
#define PH0_OFF 0u
#define PH1_OFF 9216u
#define SL_OFF 18432u
#define KV_OFF 19456u
#define KV_VH 33792u               // K tile bytes (64*528)
#define KVBUF_BYTES 70656u         // K 33792 + Vh 36864
#define ATT_SMEM (KV_OFF + 3u * KVBUF_BYTES)   // 231424

// fc smem (32-col k-chunks, 2 CTAs/SM)
#define FC_AH 0u
#define FC_AL 10240u
#define FC_BH 20480u
#define FC_BL 30720u
#define FC_BUF 40960u
#define FC_SMEM (2u * FC_BUF)   // 81920

// ---------------- device scratch ----------------
__device__ __align__(16) __half g_qh[(size_t)B * T * E];
__device__ __align__(16) __half g_kh[(size_t)B * T * E];
__device__ __align__(16) __half g_vh[(size_t)B * E * T];     // [B,d,t]
__device__ __align__(16) __half g_oh[(size_t)B * T * E];
__device__ __align__(16) __half g_ol[(size_t)B * T * E];
__device__ __align__(16) __half g_wh[E * E];
__device__ __align__(16) __half g_wl[E * E];

// ---------------- helpers ----------------
__device__ __forceinline__ uint32_t smem_u32(const void* p) {
    uint32_t a;
    asm("{ .reg .u64 t; cvta.to.shared.u64 t, %1; cvt.u32.u64 %0, t; }" : "=r"(a) : "l"(p));
    return a;
}
__device__ __forceinline__ void ldsm_x4(uint32_t* r, uint32_t a) {
    asm volatile("ldmatrix.sync.aligned.m8n8.x4.shared.b16 {%0,%1,%2,%3}, [%4];"
        : "=r"(r[0]), "=r"(r[1]), "=r"(r[2]), "=r"(r[3]) : "r"(a));
}
__device__ __forceinline__ void ldsm_x2(uint32_t* r, uint32_t a) {
    asm volatile("ldmatrix.sync.aligned.m8n8.x2.shared.b16 {%0,%1}, [%2];"
        : "=r"(r[0]), "=r"(r[1]) : "r"(a));
}
__device__ __forceinline__ void mma16816(float* d, const uint32_t* a, const uint32_t* b) {
    asm volatile("mma.sync.aligned.m16n8k16.row.col.f32.f16.f16.f32 "
        "{%0,%1,%2,%3}, {%4,%5,%6,%7}, {%8,%9}, {%0,%1,%2,%3};"
        : "+f"(d[0]), "+f"(d[1]), "+f"(d[2]), "+f"(d[3])
        : "r"(a[0]), "r"(a[1]), "r"(a[2]), "r"(a[3]), "r"(b[0]), "r"(b[1]));
}
__device__ __forceinline__ void cp16(uint32_t dst, const void* src) {
    asm volatile("cp.async.cg.shared.global [%0], [%1], 16;" :: "r"(dst), "l"(src));
}
#define CP_COMMIT()   asm volatile("cp.async.commit_group;" ::: "memory")
#define CP_WAIT1()    asm volatile("cp.async.wait_group 1;" ::: "memory")
#define CP_WAIT_ALL() asm volatile("cp.async.wait_group 0;" ::: "memory")

__device__ __forceinline__ uint32_t pack_h16(float a, float b) {
    __half2 t = __floats2half2_rn(a, b);
    return *reinterpret_cast<uint32_t*>(&t);
}

// ---------------------------------------------------------------------------
// Kernel 1: grouped conv1d, one projection per block. 3 CTAs/SM.
// ---------------------------------------------------------------------------
#define CSTG 34   // half staging stride (even -> half2 aligned)
__global__ __launch_bounds__(256, 3) void conv_qkv_kernel(
    const float* __restrict__ x,
    const float* __restrict__ wq, const float* __restrict__ bq,
    const float* __restrict__ wk, const float* __restrict__ bk,
    const float* __restrict__ wv, const float* __restrict__ bv)
{
    extern __shared__ float sm[];
    float* sx  = sm;                                 // 32*258 = 8256 floats
    float* swT = sx + GC * (CTT + 2);                // 3072 floats
    __half* st = (__half*)(swT + GC * GC * KW);      // 256*34 halves

    const int tid = threadIdx.x;
    const int b = blockIdx.z;
    const int proj = blockIdx.y / H;
    const int g = blockIdx.y % H;
    const int t0 = blockIdx.x * CTT;

    const float* wsrc = (proj == 0) ? wq : (proj == 1) ? wk : wv;
    const float* bsrc = (proj == 0) ? bq : (proj == 1) ? bk : bv;

    const int gw = g * GC * GC * KW;
    for (int i = tid; i < GC * GC * KW; i += 256) {
        int oc = i & 31, r = i >> 5;
        swT[r * 32 + oc] = wsrc[gw + oc * (GC * KW) + r];
    }
    for (int i = tid; i < GC * (CTT + 2); i += 256) {
        int ic = i / (CTT + 2), tt = i % (CTT + 2);
        int t = t0 + tt - 1;
        sx[i] = (t >= 0 && t < T) ? x[((size_t)b * E + g * GC + ic) * T + t] : 0.f;
    }
    __syncthreads();

    float acc[GC];
#pragma unroll
    for (int oc = 0; oc < GC; oc++) acc[oc] = 0.f;

    const int p = tid;
    for (int ic = 0; ic < GC; ic++) {
        float xk[3];
        xk[0] = sx[ic * (CTT + 2) + p];
        xk[1] = sx[ic * (CTT + 2) + p + 1];
        xk[2] = sx[ic * (CTT + 2) + p + 2];
#pragma unroll
        for (int kw = 0; kw < 3; kw++) {
            const float* wrow = &swT[(ic * 3 + kw) * 32];
#pragma unroll
            for (int oc4 = 0; oc4 < 8; oc4++) {
                float4 w4 = *(const float4*)&wrow[oc4 * 4];
                acc[oc4 * 4 + 0] += xk[kw] * w4.x;
                acc[oc4 * 4 + 1] += xk[kw] * w4.y;
                acc[oc4 * 4 + 2] += xk[kw] * w4.z;
                acc[oc4 * 4 + 3] += xk[kw] * w4.w;
            }
        }
    }

    if (proj == 2) {
#pragma unroll
        for (int oc = 0; oc < GC; oc++) {
            float v = acc[oc] + bsrc[g * GC + oc];
            g_vh[((size_t)b * E + g * GC + oc) * T + t0 + p] = __float2half(v);
        }
        return;
    }

    // stage [t][oc] as half for coalesced half2 writes
#pragma unroll
    for (int oc = 0; oc < GC; oc++)
        st[p * CSTG + oc] = __float2half(acc[oc] + bsrc[g * GC + oc]);
    __syncthreads();

    __half* dst = (proj == 0) ? g_qh : g_kh;
    const size_t ob = ((size_t)b * T + t0) * E + g * GC;
    for (int i = tid; i < CTT * 16; i += 256) {
        int t = i >> 4, oc2 = i & 15;
        uint32_t v = *(const uint32_t*)&st[t * CSTG + oc2 * 2];
        *(uint32_t*)&dst[ob + (size_t)t * E + oc2 * 2] = v;
    }
}

// ---------------------------------------------------------------------------
// Kernel 1b: split w_fc into fp16 hi/lo
// ---------------------------------------------------------------------------
__global__ void wsplit_kernel(const float* __restrict__ wfc)
{
    int i = blockIdx.x * 256 + threadIdx.x;
    float v = wfc[i];
    __half hi = __float2half(v);
    g_wh[i] = hi;
    g_wl[i] = __float2half(v - __half2float(hi));
}

// ---------------------------------------------------------------------------
// Kernel 2: flash attention, skewed pipeline (unchanged from R16).
// ---------------------------------------------------------------------------
__device__ __forceinline__ void load_tile_kv(uint32_t sb, int b, int t, int buf, int tid)
{
    const uint32_t base = sb + KV_OFF + (uint32_t)buf * KVBUF_BYTES;
    const char* ksrc = (const char*)(g_kh + ((size_t)(b * T + t * KN)) * E);
    for (int i = tid; i < 2048; i += 256) {
        int key = i >> 5, c = i & 31;
        cp16(base + key * 528 + c * 16, ksrc + (size_t)key * 512 + c * 16);
    }
    const char* vhsrc = (const char*)(g_vh + (size_t)b * E * T + (size_t)t * KN);
    for (int i = tid; i < 2048; i += 256) {
        int d = i >> 3, c = i & 7;
        cp16(base + KV_VH + d * 144 + c * 16, vhsrc + (size_t)d * T * 2 + c * 16);
    }
    CP_COMMIT();
}

__global__ __launch_bounds__(256, 1) void attn_kernel()
{
    extern __shared__ char smem[];
    const uint32_t sb = smem_u32(smem);
    float* sL = (float*)(smem + SL_OFF);     // [2][64]

    const int tid = threadIdx.x;
    const int wid = tid >> 5, lane = tid & 31;
    const int b = blockIdx.y;
    const int q0 = blockIdx.x * QM;
    const float scale = 0.0625f;

    const int r0 = (wid >> 1) * 16, c0 = (wid & 1) * 32;
    const int rr0 = (wid >> 2) * 32, dd0 = (wid & 3) * 64;

    const uint32_t qrow = (uint32_t)(lane & 15);
    const uint32_t qcchunk = (uint32_t)((lane >> 4) << 3);
    const uint32_t brow8 = (uint32_t)((lane & 7) + ((lane >> 4) << 3));
    const uint32_t bcol8 = (uint32_t)(lane & 8);

    // ---- stage Q into KV area, ldmatrix into registers, then release ----
    uint32_t qf[16][4];
    {
        for (int i = tid; i < 2048; i += 256) {
            int r = i >> 5, c8 = i & 31;
            *(uint4*)(smem + KV_OFF + r * (QSTR * 2) + c8 * 16) =
                *(const uint4*)((const char*)(g_qh + ((size_t)(b * T + q0 + r)) * E) + c8 * 16);
        }
        __syncthreads();
#pragma unroll
        for (int kk = 0; kk < 16; kk++)
            ldsm_x4(qf[kk], sb + KV_OFF +
                    (((uint32_t)r0 + qrow) * QSTR + kk * 16 + qcchunk) * 2);
        __syncthreads();
    }

    load_tile_kv(sb, b, 0, 0, tid);
    load_tile_kv(sb, b, 1, 1, tid);

    float oacc[2][8][4];
#pragma unroll
    for (int mi = 0; mi < 2; mi++)
#pragma unroll
        for (int j = 0; j < 8; j++)
#pragma unroll
            for (int e = 0; e < 4; e++) oacc[mi][j][e] = 0.f;
    float lsum[2] = {0.f, 0.f};
    float sacc[4][4];

    // ---- preamble: S(0) ----
    CP_WAIT1();
    __syncthreads();
#pragma unroll
    for (int j = 0; j < 4; j++)
#pragma unroll
        for (int e = 0; e < 4; e++) sacc[j][e] = 0.f;
    {
        const uint32_t kb = sb + KV_OFF;
#pragma unroll
        for (int kk = 0; kk < 16; kk++) {
            const int d0 = kk * 16;
#pragma unroll
            for (int jp = 0; jp < 2; jp++) {
                uint32_t key = (uint32_t)(c0 + 16 * jp) + brow8;
                uint32_t bb[4];
                ldsm_x4(bb, kb + (key * KSTR + d0 + bcol8) * 2);
                mma16816(sacc[2 * jp],     qf[kk], bb);
                mma16816(sacc[2 * jp + 1], qf[kk], bb + 2);
            }
        }
    }

    int bufv = 0, bufk = 1, bufl = 2;
    for (int t = 0; t < NT; t++) {
        char* php = smem + ((t & 1) ? PH1_OFF : PH0_OFF);
        const uint32_t phs = sb + ((t & 1) ? PH1_OFF : PH0_OFF);
#pragma unroll
        for (int j = 0; j < 4; j++) {
            float p0 = __expf(sacc[j][0] * scale);
            float p1 = __expf(sacc[j][1] * scale);
            float p2 = __expf(sacc[j][2] * scale);
            float p3 = __expf(sacc[j][3] * scale);
            lsum[0] += p0 + p1;
            lsum[1] += p2 + p3;
            int row = r0 + (lane >> 2);
            int col = c0 + 8 * j + ((lane & 3) << 1);
            *(uint32_t*)(php + row * (PSTR * 2) + col * 2) = pack_h16(p0, p1);
            *(uint32_t*)(php + (row + 8) * (PSTR * 2) + col * 2) = pack_h16(p2, p3);
        }

        CP_WAIT_ALL();
        __syncthreads();
        if (t + 2 < NT) load_tile_kv(sb, b, t + 2, bufl, tid);

        const uint32_t vb = sb + KV_OFF + (uint32_t)bufv * KVBUF_BYTES + KV_VH;

#pragma unroll
        for (int kk2 = 0; kk2 < 4; kk2++) {
            const int key0 = kk2 * 16;
            uint32_t ph2[2][4];
#pragma unroll
            for (int mi = 0; mi < 2; mi++) {
                uint32_t prow = (uint32_t)(rr0 + 16 * mi) + qrow;
                ldsm_x4(ph2[mi], phs + (prow * PSTR + key0 + qcchunk) * 2);
            }
#pragma unroll
            for (int jp = 0; jp < 4; jp++) {
                uint32_t drow = (uint32_t)(dd0 + 16 * jp) + brow8;
                uint32_t bb[4];
                ldsm_x4(bb, vb + (drow * VSTR + key0 + bcol8) * 2);
#pragma unroll
                for (int mi = 0; mi < 2; mi++) {
                    mma16816(oacc[mi][2 * jp],     ph2[mi], bb);
                    mma16816(oacc[mi][2 * jp + 1], ph2[mi], bb + 2);
                }
            }
        }

        if (t + 1 < NT) {
            const uint32_t kb = sb + KV_OFF + (uint32_t)bufk * KVBUF_BYTES;
#pragma unroll
            for (int j = 0; j < 4; j++)
#pragma unroll
                for (int e = 0; e < 4; e++) sacc[j][e] = 0.f;
#pragma unroll
            for (int kk = 0; kk < 16; kk++) {
                const int d0 = kk * 16;
#pragma unroll
                for (int jp = 0; jp < 2; jp++) {
                    uint32_t key = (uint32_t)(c0 + 16 * jp) + brow8;
                    uint32_t bb[4];
                    ldsm_x4(bb, kb + (key * KSTR + d0 + bcol8) * 2);
                    mma16816(sacc[2 * jp],     qf[kk], bb);
                    mma16816(sacc[2 * jp + 1], qf[kk], bb + 2);
                }
            }
        }

        int tmp = bufv; bufv = bufk; bufk = bufl; bufl = tmp;
    }

    // ---- l reduction ----
    lsum[0] += __shfl_xor_sync(0xffffffffu, lsum[0], 1);
    lsum[0] += __shfl_xor_sync(0xffffffffu, lsum[0], 2);
    lsum[1] += __shfl_xor_sync(0xffffffffu, lsum[1], 1);
    lsum[1] += __shfl_xor_sync(0xffffffffu, lsum[1], 2);
    __syncthreads();
    if ((lane & 3) == 0) {
        sL[(wid & 1) * 64 + r0 + (lane >> 2)] = lsum[0];
        sL[(wid & 1) * 64 + r0 + 8 + (lane >> 2)] = lsum[1];
    }
    __syncthreads();

    // ---- O /= l, write fp16 hi/lo ----
#pragma unroll
    for (int mi = 0; mi < 2; mi++) {
        int rA = rr0 + 16 * mi + (lane >> 2);
        int rB = rA + 8;
        float invA = 1.f / (sL[rA] + sL[64 + rA]);
        float invB = 1.f / (sL[rB] + sL[64 + rB]);
        size_t oa = ((size_t)(b * T + q0 + rA)) * E;
        size_t ob = ((size_t)(b * T + q0 + rB)) * E;
#pragma unroll
        for (int j = 0; j < 8; j++) {
            int col = dd0 + 8 * j + ((lane & 3) << 1);
            float a0 = oacc[mi][j][0] * invA, a1 = oacc[mi][j][1] * invA;
            float b0 = oacc[mi][j][2] * invB, b1 = oacc[mi][j][3] * invB;
            __half ha0 = __float2half(a0), ha1 = __float2half(a1);
            __half hb0 = __float2half(b0), hb1 = __float2half(b1);
            *(uint32_t*)(g_oh + oa + col) = pack_h16(a0, a1);
            *(uint32_t*)(g_ol + oa + col) =
                pack_h16(a0 - __half2float(ha0), a1 - __half2float(ha1));
            *(uint32_t*)(g_oh + ob + col) = pack_h16(b0, b1);
            *(uint32_t*)(g_ol + ob + col) =
                pack_h16(b0 - __half2float(hb0), b1 - __half2float(hb1));
        }
    }
}

// ---------------------------------------------------------------------------
// Kernel 3: fc_out via fp16 mma 3-term. CTA 128r x 128c, K in 8 chunks of 32.
// 2 CTAs/SM (80 KB smem).
// ---------------------------------------------------------------------------
__device__ __forceinline__ void load_fc(uint32_t sb, int r0, int c0, int c, int buf, int tid)
{
    const uint32_t base = sb + (uint32_t)buf * FC_BUF;
    for (int i = tid; i < 512; i += 256) {
        int row = i >> 2, seg = i & 3;
        const size_t ao = (size_t)(r0 + row) * E + c * 32;
        const size_t bo = (size_t)(c0 + row) * E + c * 32;
        cp16(base + FC_AH + row * 80 + seg * 16, (const char*)(g_oh + ao) + seg * 16);
        cp16(base + FC_AL + row * 80 + seg * 16, (const char*)(g_ol + ao) + seg * 16);
        cp16(base + FC_BH + row * 80 + seg * 16, (const char*)(g_wh + bo) + seg * 16);
        cp16(base + FC_BL + row * 80 + seg * 16, (const char*)(g_wl + bo) + seg * 16);
    }
    CP_COMMIT();
}

__global__ __launch_bounds__(256, 2) void fc_kernel(
    const float* __restrict__ bfc, float* __restrict__ out)
{
    extern __shared__ char smem[];
    const uint32_t sb = smem_u32(smem);

    const int tid = threadIdx.x;
    const int wid = tid >> 5, lane = tid & 31;
    const int r0 = blockIdx.y * 128, c0 = blockIdx.x * 128;
    const int wr2 = wid >> 1, wc2 = wid & 1;

    float acc[2][8][4];
#pragma unroll
    for (int mi = 0; mi < 2; mi++)
#pragma unroll
        for (int j = 0; j < 8; j++)
#pragma unroll
            for (int e = 0; e < 4; e++) acc[mi][j][e] = 0.f;

    const uint32_t qrow = (uint32_t)(lane & 15);
    const uint32_t qcchunk = (uint32_t)((lane >> 4) << 3);

    load_fc(sb, r0, c0, 0, 0, tid);

    for (int c = 0; c < 8; c++) {
        if (c + 1 < 8) load_fc(sb, r0, c0, c + 1, (c + 1) & 1, tid);
        else CP_COMMIT();
        CP_WAIT1();
        __syncthreads();
        const uint32_t base = sb + (uint32_t)(c & 1) * FC_BUF;

#pragma unroll
        for (int kk = 0; kk < 2; kk++) {
            const int d0 = kk * 16;
            uint32_t ah[2][4], al[2][4];
#pragma unroll
            for (int mi = 0; mi < 2; mi++) {
                uint32_t aaddr = base + FC_AH +
                    (((uint32_t)(wr2 * 32 + mi * 16) + qrow) * 40 + d0 + qcchunk) * 2;
                ldsm_x4(ah[mi], aaddr);
                ldsm_x4(al[mi], aaddr + (FC_AL - FC_AH));
            }
#pragma unroll
            for (int j = 0; j < 8; j++) {
                uint32_t brow = (uint32_t)(wc2 * 64 + 8 * j + (lane & 7));
                uint32_t baddr = base + FC_BH + (brow * 40 + d0 + (lane & 8)) * 2;
                uint32_t bh[2], bl[2];
                ldsm_x2(bh, baddr);
                ldsm_x2(bl, baddr + (FC_BL - FC_BH));
#pragma unroll
                for (int mi = 0; mi < 2; mi++) {
                    mma16816(acc[mi][j], ah[mi], bh);
                    mma16816(acc[mi][j], al[mi], bh);
                    mma16816(acc[mi][j], ah[mi], bl);
                }
            }
        }
        __syncthreads();
    }

#pragma unroll
    for (int mi = 0; mi < 2; mi++) {
        int rA = r0 + wr2 * 32 + mi * 16 + (lane >> 2);
        int rB = rA + 8;
#pragma unroll
        for (int j = 0; j < 8; j++) {
            int o = c0 + wc2 * 64 + 8 * j + ((lane & 3) << 1);
            float b0 = bfc[o], b1 = bfc[o + 1];
            *(float2*)&out[(size_t)rA * E + o] =
                make_float2(acc[mi][j][0] + b0, acc[mi][j][1] + b1);
            *(float2*)&out[(size_t)rB * E + o] =
                make_float2(acc[mi][j][2] + b0, acc[mi][j][3] + b1);
        }
    }
}

// ---------------------------------------------------------------------------

extern "C" void kernel_launch(void* const* d_in, const int* in_sizes, int n_in,
                              void* d_out, int out_size)
{
    const float* x   = (const float*)d_in[0];
    const float* wq  = (const float*)d_in[1];
    const float* bq  = (const float*)d_in[2];
    const float* wk  = (const float*)d_in[3];
    const float* bk  = (const float*)d_in[4];
    const float* wv  = (const float*)d_in[5];
    const float* bv  = (const float*)d_in[6];
    const float* wfc = (const float*)d_in[7];
    const float* bfc = (const float*)d_in[8];
    float* out = (float*)d_out;

    // conv smem: sx (8256 f) + swT (3072 f) + staging (256*34 halves)
    const int conv_smem = (GC * (CTT + 2) + GC * GC * KW) * 4 + 256 * CSTG * 2;

    cudaFuncSetAttribute(conv_qkv_kernel, cudaFuncAttributeMaxDynamicSharedMemorySize, conv_smem);
    cudaFuncSetAttribute(attn_kernel, cudaFuncAttributeMaxDynamicSharedMemorySize, ATT_SMEM);
    cudaFuncSetAttribute(fc_kernel, cudaFuncAttributeMaxDynamicSharedMemorySize, FC_SMEM);

    conv_qkv_kernel<<<dim3(T / CTT, 3 * H, B), 256, conv_smem>>>(x, wq, bq, wk, bk, wv, bv);
    wsplit_kernel<<<E * E / 256, 256>>>(wfc);
    attn_kernel<<<dim3(T / QM, B), 256, ATT_SMEM>>>();
    fc_kernel<<<dim3(E / 128, (B * T) / 128), 256, FC_SMEM>>>(bfc, out);
}